// round 4
// baseline (speedup 1.0000x reference)
#include <cuda_runtime.h>
#include <math.h>

// KMeans assignment: out[i] = argmin_k ( cnorm[k] - 2 * dot(X[i,:], C[:,k]) )
// N=131072, D=768, K=2048, fp32 inputs. Output: argmin index stored as FLOAT32
// (the harness's __output__ dtype — int bit-patterns read back as denormals,
// which is what produced the exact rel_err=1.0 in rounds 2/3).
//
// 128x128 block tile, BK=16 slab, 256 threads, 8x8 micro-tile.
// Double-buffered smem + register prefetch: one __syncthreads per slab.

#define N_ROWS 131072
#define D_DIM  768
#define K_CENT 2048

#define BM 128
#define BN 128
#define BK 16
#define TM 8
#define TN 8
#define NTHREADS 256
#define NSLABS (D_DIM / BK)   // 48

__global__ __launch_bounds__(NTHREADS, 2)
void kmeans_assign_kernel(const float* __restrict__ X,
                          const float* __restrict__ C,
                          const float* __restrict__ cnorm,
                          float* __restrict__ out)
{
    __shared__ float Xs[2][BK][BM + 4];
    __shared__ float Cs[2][BK][BN];

    const int tid = threadIdx.x;
    const int block_row = blockIdx.x * BM;

    const int tr = (tid >> 4) * TM;    // micro-tile row offset
    const int tc = (tid & 15) * TN;    // micro-tile col offset

    // Fixed per-thread load coordinates (2 float4 each for X and C)
    const int xm0 = tid >> 2;          // X row (l=0); l=1 adds 64
    const int xd  = (tid & 3) * 4;     // d offset within slab
    const int cd0 = tid >> 5;          // C d-row (l=0); l=1 adds 8
    const int ck  = (tid & 31) * 4;    // k offset within tile

    float bestv[TM];
    int   besti[TM];
#pragma unroll
    for (int i = 0; i < TM; i++) { bestv[i] = INFINITY; besti[i] = 0; }

    for (int k0 = 0; k0 < K_CENT; k0 += BN) {
        float acc[TM][TN];
#pragma unroll
        for (int i = 0; i < TM; i++)
#pragma unroll
            for (int j = 0; j < TN; j++) acc[i][j] = 0.0f;

        // ---- prologue: slab 0 -> buffer 0 ----
        {
            float4 xv0 = *(const float4*)&X[(size_t)(block_row + xm0)      * D_DIM + xd];
            float4 xv1 = *(const float4*)&X[(size_t)(block_row + xm0 + 64) * D_DIM + xd];
            float4 cv0 = *(const float4*)&C[(size_t)(cd0)     * K_CENT + k0 + ck];
            float4 cv1 = *(const float4*)&C[(size_t)(cd0 + 8) * K_CENT + k0 + ck];
            Xs[0][xd+0][xm0] = xv0.x; Xs[0][xd+1][xm0] = xv0.y;
            Xs[0][xd+2][xm0] = xv0.z; Xs[0][xd+3][xm0] = xv0.w;
            Xs[0][xd+0][xm0+64] = xv1.x; Xs[0][xd+1][xm0+64] = xv1.y;
            Xs[0][xd+2][xm0+64] = xv1.z; Xs[0][xd+3][xm0+64] = xv1.w;
            *(float4*)&Cs[0][cd0][ck]     = cv0;
            *(float4*)&Cs[0][cd0 + 8][ck] = cv1;
        }
        __syncthreads();

        for (int s = 0; s < NSLABS; s++) {
            const int cur = s & 1;
            const int nxt = cur ^ 1;
            const int d0n = (s + 1) * BK;

            // ---- prefetch next slab into registers ----
            float4 xv0, xv1, cv0, cv1;
            if (s + 1 < NSLABS) {
                xv0 = *(const float4*)&X[(size_t)(block_row + xm0)      * D_DIM + d0n + xd];
                xv1 = *(const float4*)&X[(size_t)(block_row + xm0 + 64) * D_DIM + d0n + xd];
                cv0 = *(const float4*)&C[(size_t)(d0n + cd0)     * K_CENT + k0 + ck];
                cv1 = *(const float4*)&C[(size_t)(d0n + cd0 + 8) * K_CENT + k0 + ck];
            }

            // ---- FMA micro-kernel over current slab ----
#pragma unroll
            for (int d = 0; d < BK; d++) {
                float xr[TM], cr[TN];
#pragma unroll
                for (int i = 0; i < TM; i++) xr[i] = Xs[cur][d][tr + i];
#pragma unroll
                for (int j = 0; j < TN; j++) cr[j] = Cs[cur][d][tc + j];
#pragma unroll
                for (int i = 0; i < TM; i++)
#pragma unroll
                    for (int j = 0; j < TN; j++)
                        acc[i][j] = fmaf(xr[i], cr[j], acc[i][j]);
            }

            // ---- commit prefetched slab ----
            if (s + 1 < NSLABS) {
                Xs[nxt][xd+0][xm0] = xv0.x; Xs[nxt][xd+1][xm0] = xv0.y;
                Xs[nxt][xd+2][xm0] = xv0.z; Xs[nxt][xd+3][xm0] = xv0.w;
                Xs[nxt][xd+0][xm0+64] = xv1.x; Xs[nxt][xd+1][xm0+64] = xv1.y;
                Xs[nxt][xd+2][xm0+64] = xv1.z; Xs[nxt][xd+3][xm0+64] = xv1.w;
                *(float4*)&Cs[nxt][cd0][ck]     = cv0;
                *(float4*)&Cs[nxt][cd0 + 8][ck] = cv1;
            }
            __syncthreads();
        }

        // ---- fold K-chunk into running argmin (ascending k, strict <) ----
#pragma unroll
        for (int j = 0; j < TN; j++) {
            int k = k0 + tc + j;
            float cn = __ldg(&cnorm[k]);
#pragma unroll
            for (int i = 0; i < TM; i++) {
                float s = fmaf(-2.0f, acc[i][j], cn);
                if (s < bestv[i]) { bestv[i] = s; besti[i] = k; }
            }
        }
    }

    // ---- reduce across 16 threads sharing each row ----
#pragma unroll
    for (int i = 0; i < TM; i++) {
        float v  = bestv[i];
        int   bi = besti[i];
#pragma unroll
        for (int off = 8; off > 0; off >>= 1) {
            float ov = __shfl_down_sync(0xffffffffu, v,  off, 16);
            int   oi = __shfl_down_sync(0xffffffffu, bi, off, 16);
            if (ov < v || (ov == v && oi < bi)) { v = ov; bi = oi; }
        }
        if ((tid & 15) == 0) out[block_row + tr + i] = (float)bi;
    }
}

extern "C" void kernel_launch(void* const* d_in, const int* in_sizes, int n_in,
                              void* d_out, int out_size)
{
    // Resolve inputs by element count (robust to metadata ordering):
    //   x:             131072*768 = 100663296
    //   centroids:     768*2048   = 1572864
    //   centroid_norm: 2048
    const float* X = nullptr;
    const float* C = nullptr;
    const float* cnorm = nullptr;
    for (int i = 0; i < n_in; i++) {
        if      (in_sizes[i] == N_ROWS * D_DIM) X     = (const float*)d_in[i];
        else if (in_sizes[i] == D_DIM * K_CENT) C     = (const float*)d_in[i];
        else if (in_sizes[i] == K_CENT)         cnorm = (const float*)d_in[i];
    }
    float* out = (float*)d_out;   // __output__ dtype: float32 (indices as floats)

    dim3 grid(N_ROWS / BM);   // 1024 blocks
    dim3 block(NTHREADS);
    kmeans_assign_kernel<<<grid, block>>>(X, C, cnorm, out);
}

// round 7
// speedup vs baseline: 1.0433x; 1.0433x over previous
#include <cuda_runtime.h>
#include <math.h>
#include <stdint.h>

// KMeans assignment: out[i] = argmin_k ( cnorm[k] - 2 * dot(X[i,:], C[:,k]) )
// N=131072, D=768, K=2048, fp32. Output: index as float32.
//
// 128x128 tile, BK=16, 256 threads, 8x8 micro-tile, double-buffered smem.
// R6: R5 theory without cp.async (plain LDG/STS, proven-to-run construct set).
// Two-stage LDS pipeline, besti in smem, Xs pad=+1 (conflict-free stores,
// 16B-aligned rows so xr/cr vectorize to LDS.128).

#define N_ROWS 131072
#define D_DIM  768
#define K_CENT 2048

#define BM 128
#define BN 128
#define BK 16
#define TM 8
#define TN 8
#define NTHREADS 256
#define NSLABS (D_DIM / BK)   // 48
#define XPAD 4                // row = 132 floats = 528B (16B-aligned rows)

__global__ __launch_bounds__(NTHREADS, 2)
void kmeans_assign_kernel(const float* __restrict__ X,
                          const float* __restrict__ C,
                          const float* __restrict__ cnorm,
                          float* __restrict__ out)
{
    __shared__ float Xs[2][BK][BM + XPAD];  // 16896 B
    __shared__ float Cs[2][BK][BN];         // 16384 B
    __shared__ int   besti_s[TM][NTHREADS]; //  8192 B  (total 41472 B < 48K)

    const int tid = threadIdx.x;
    const int block_row = blockIdx.x * BM;

    const int tr = (tid >> 4) * TM;    // micro-tile row offset
    const int tc = (tid & 15) * TN;    // micro-tile col offset

    // X load coords (2 float4 per thread; transposed store)
    const int xm0 = tid >> 2;          // row (l=0); l=1 adds 64
    const int xd  = (tid & 3) * 4;     // d offset within slab
    // C load coords (2 float4 per thread; layout-preserving store)
    const int cd0 = tid >> 5;          // d-row (l=0); l=1 adds 8
    const int ck  = (tid & 31) * 4;    // k offset within tile

    float bestv[TM];
#pragma unroll
    for (int i = 0; i < TM; i++) { bestv[i] = INFINITY; besti_s[i][tid] = 0; }

    for (int k0 = 0; k0 < K_CENT; k0 += BN) {
        float acc[TM][TN];
#pragma unroll
        for (int i = 0; i < TM; i++)
#pragma unroll
            for (int j = 0; j < TN; j++) acc[i][j] = 0.0f;

        // ---- prologue: slab 0 -> buffer 0 ----
        {
            float4 xv0 = *(const float4*)&X[(size_t)(block_row + xm0)      * D_DIM + xd];
            float4 xv1 = *(const float4*)&X[(size_t)(block_row + xm0 + 64) * D_DIM + xd];
            float4 cv0 = *(const float4*)&C[(size_t)(cd0)     * K_CENT + k0 + ck];
            float4 cv1 = *(const float4*)&C[(size_t)(cd0 + 8) * K_CENT + k0 + ck];
            Xs[0][xd+0][xm0] = xv0.x; Xs[0][xd+1][xm0] = xv0.y;
            Xs[0][xd+2][xm0] = xv0.z; Xs[0][xd+3][xm0] = xv0.w;
            Xs[0][xd+0][xm0+64] = xv1.x; Xs[0][xd+1][xm0+64] = xv1.y;
            Xs[0][xd+2][xm0+64] = xv1.z; Xs[0][xd+3][xm0+64] = xv1.w;
            *(float4*)&Cs[0][cd0][ck]     = cv0;
            *(float4*)&Cs[0][cd0 + 8][ck] = cv1;
        }
        __syncthreads();

        for (int s = 0; s < NSLABS; s++) {
            const int cur = s & 1;
            const int nxt = cur ^ 1;
            const int d0n = (s + 1) * BK;

            // ---- prefetch next slab into registers ----
            float4 xv0, xv1, cv0, cv1;
            if (s + 1 < NSLABS) {
                xv0 = *(const float4*)&X[(size_t)(block_row + xm0)      * D_DIM + d0n + xd];
                xv1 = *(const float4*)&X[(size_t)(block_row + xm0 + 64) * D_DIM + d0n + xd];
                cv0 = *(const float4*)&C[(size_t)(d0n + cd0)     * K_CENT + k0 + ck];
                cv1 = *(const float4*)&C[(size_t)(d0n + cd0 + 8) * K_CENT + k0 + ck];
            }

            // ---- FMA micro-kernel, two-stage LDS pipeline over d ----
            float xr[2][TM], cr[2][TN];
#pragma unroll
            for (int i = 0; i < TM; i += 4)
                *(float4*)&xr[0][i] = *(const float4*)&Xs[cur][0][tr + i];
#pragma unroll
            for (int j = 0; j < TN; j += 4)
                *(float4*)&cr[0][j] = *(const float4*)&Cs[cur][0][tc + j];

#pragma unroll
            for (int d = 0; d < BK; d++) {
                const int pc = d & 1;
                const int pn = pc ^ 1;
                if (d + 1 < BK) {
#pragma unroll
                    for (int i = 0; i < TM; i += 4)
                        *(float4*)&xr[pn][i] = *(const float4*)&Xs[cur][d + 1][tr + i];
#pragma unroll
                    for (int j = 0; j < TN; j += 4)
                        *(float4*)&cr[pn][j] = *(const float4*)&Cs[cur][d + 1][tc + j];
                }
#pragma unroll
                for (int i = 0; i < TM; i++)
#pragma unroll
                    for (int j = 0; j < TN; j++)
                        acc[i][j] = fmaf(xr[pc][i], cr[pc][j], acc[i][j]);
            }

            // ---- commit prefetched slab ----
            if (s + 1 < NSLABS) {
                Xs[nxt][xd+0][xm0] = xv0.x; Xs[nxt][xd+1][xm0] = xv0.y;
                Xs[nxt][xd+2][xm0] = xv0.z; Xs[nxt][xd+3][xm0] = xv0.w;
                Xs[nxt][xd+0][xm0+64] = xv1.x; Xs[nxt][xd+1][xm0+64] = xv1.y;
                Xs[nxt][xd+2][xm0+64] = xv1.z; Xs[nxt][xd+3][xm0+64] = xv1.w;
                *(float4*)&Cs[nxt][cd0][ck]     = cv0;
                *(float4*)&Cs[nxt][cd0 + 8][ck] = cv1;
            }
            __syncthreads();
        }

        // ---- fold K-chunk into running argmin (ascending k, strict <) ----
#pragma unroll
        for (int j = 0; j < TN; j++) {
            int k = k0 + tc + j;
            float cn = __ldg(&cnorm[k]);
#pragma unroll
            for (int i = 0; i < TM; i++) {
                float s = fmaf(-2.0f, acc[i][j], cn);
                if (s < bestv[i]) { bestv[i] = s; besti_s[i][tid] = k; }
            }
        }
    }

    // ---- reduce across 16 threads sharing each row ----
#pragma unroll
    for (int i = 0; i < TM; i++) {
        float v  = bestv[i];
        int   bi = besti_s[i][tid];
#pragma unroll
        for (int off = 8; off > 0; off >>= 1) {
            float ov = __shfl_down_sync(0xffffffffu, v,  off, 16);
            int   oi = __shfl_down_sync(0xffffffffu, bi, off, 16);
            if (ov < v || (ov == v && oi < bi)) { v = ov; bi = oi; }
        }
        if ((tid & 15) == 0) out[block_row + tr + i] = (float)bi;
    }
}

extern "C" void kernel_launch(void* const* d_in, const int* in_sizes, int n_in,
                              void* d_out, int out_size)
{
    const float* X = nullptr;
    const float* C = nullptr;
    const float* cnorm = nullptr;
    for (int i = 0; i < n_in; i++) {
        if      (in_sizes[i] == N_ROWS * D_DIM) X     = (const float*)d_in[i];
        else if (in_sizes[i] == D_DIM * K_CENT) C     = (const float*)d_in[i];
        else if (in_sizes[i] == K_CENT)         cnorm = (const float*)d_in[i];
    }
    float* out = (float*)d_out;

    dim3 grid(N_ROWS / BM);   // 1024 blocks
    dim3 block(NTHREADS);
    kmeans_assign_kernel<<<grid, block>>>(X, C, cnorm, out);
}